// round 15
// baseline (speedup 1.0000x reference)
#include <cuda_runtime.h>
#include <cstdint>

#define MAXB 4096

static __device__ float g_pos[MAXB];
static __device__ float g_part[64 * MAXB];   // [part = colTile*8 + cw][row]
static __device__ unsigned g_done = 0;

__device__ __forceinline__ float ex2f(float x) {
    float r; asm("ex2.approx.f32 %0, %1;" : "=f"(r) : "f"(x)); return r;
}
__device__ __forceinline__ float lg2f(float x) {
    float r; asm("lg2.approx.f32 %0, %1;" : "=f"(r) : "f"(x)); return r;
}

// m16n8k8 TF32 MMA: D = A(16x8,row) * B(8x8,col) + D, fp32 accum.
__device__ __forceinline__ void mma_tf32(float& c0, float& c1, float& c2, float& c3,
                                         uint32_t a0, uint32_t a1, uint32_t a2, uint32_t a3,
                                         uint32_t b0, uint32_t b1) {
    asm volatile(
        "mma.sync.aligned.m16n8k8.row.col.f32.tf32.tf32.f32 "
        "{%0,%1,%2,%3}, {%4,%5,%6,%7}, {%8,%9}, {%0,%1,%2,%3};"
        : "+f"(c0), "+f"(c1), "+f"(c2), "+f"(c3)
        : "r"(a0), "r"(a1), "r"(a2), "r"(a3), "r"(b0), "r"(b1));
}

#define STRIDE 132                 // 128 + 4 pad floats -> conflict-free fragment LDS
#define N_AS (64 * STRIDE)         // A: [row][k] natural, padded (33 KB)
#define N_BS (128 * STRIDE)        // B: [col][k] natural, padded (66 KB)

// ---------------- Fused kernel ----------------
// Tile 64 rows x 128 cols, 1024 threads = 32 warps, grid (B/128, B/64) = 128 CTAs.
// Warp w: row-block rw = w&3 (16 rows), col-group cw = w>>2 (16 cols = 2 n-blocks).
// K loop: 16 steps of k=8 via mma.sync m16n8k8 tf32 (fallback HMMA on sm_103).
// A smem [64][132] fp32 row-major; B smem [128][132] = zp tile [col][k] (col-major
// B as required by .row.col). Fragment scalar LDS conflict-free via the 4-float pad.
__global__ void __launch_bounds__(1024, 1)
hyp_pair(const float* __restrict__ z, const float* __restrict__ zp,
         float* __restrict__ out, int B) {
    extern __shared__ float smem_f[];
    float* As  = smem_f;                      // 33 KB
    float* Bs  = smem_f + N_AS;               // 66 KB
    float* sx2 = Bs + N_BS;                   // 64
    float* sy2 = sx2 + 64;                    // 128
    float* syi = sy2 + 128;                   // 128
    unsigned* s_rank = (unsigned*)(syi + 128);
    float*    red    = (float*)(s_rank + 8);  // 32 floats

    const int tid  = threadIdx.x;
    const int lane = tid & 31;
    const int warp = tid >> 5;                // 0..31
    const int row0 = blockIdx.y * 64;
    const int col0 = blockIdx.x * 128;

    // ---- fill A: 64 rows x 128 k (coalesced LDG, natural padded store, fused row-norm) ----
    {
        const float4* zA = (const float4*)z + row0 * 32;
        #pragma unroll
        for (int p = 0; p < 2; p++) {
            int r = p * 32 + warp;            // warp owns one full row; lanes sweep k
            float4 v = zA[r * 32 + lane];
            *(float4*)(As + r * STRIDE + 4 * lane) = v;
            float s = v.x * v.x + v.y * v.y + v.z * v.z + v.w * v.w;
            #pragma unroll
            for (int o = 16; o; o >>= 1) s += __shfl_xor_sync(0xffffffffu, s, o);
            if (lane == 0) sx2[r] = s;
        }
    }
    // ---- fill B: 128 cols x 128 k (natural padded store, fused col-norm) ----
    {
        const float4* zB = (const float4*)zp + col0 * 32;
        #pragma unroll
        for (int p = 0; p < 4; p++) {
            int cj = p * 32 + warp;
            float4 v = zB[cj * 32 + lane];
            *(float4*)(Bs + cj * STRIDE + 4 * lane) = v;
            float s = v.x * v.x + v.y * v.y + v.z * v.z + v.w * v.w;
            #pragma unroll
            for (int o = 16; o; o >>= 1) s += __shfl_xor_sync(0xffffffffu, s, o);
            if (lane == 0) {
                sy2[cj] = s;
                syi[cj] = rsqrtf(fmaxf(s, 1e-24f));   // == 1/max(norm,1e-12)
            }
        }
    }
    __syncthreads();

    const int rw  = warp & 3;                 // row-block (16 rows)
    const int cw  = warp >> 2;                // col-group (16 cols), 0..7
    const int g   = lane >> 2;                // groupID
    const int tig = lane & 3;                 // threadID-in-group

    float acc[2][4];                          // [n-block][c-frag]
    #pragma unroll
    for (int nb = 0; nb < 2; nb++)
        #pragma unroll
        for (int c = 0; c < 4; c++) acc[nb][c] = 0.0f;

    const uint32_t* A0 = (const uint32_t*)(As + (rw * 16 + g) * STRIDE + tig);
    const uint32_t* A1 = A0 + 8 * STRIDE;
    const uint32_t* Bp = (const uint32_t*)(Bs + (cw * 16 + g) * STRIDE + tig);

    #pragma unroll
    for (int ks = 0; ks < 16; ks++) {
        const int ko = ks * 8;
        uint32_t a0 = A0[ko];
        uint32_t a1 = A1[ko];
        uint32_t a2 = A0[ko + 4];
        uint32_t a3 = A1[ko + 4];
        #pragma unroll
        for (int nb = 0; nb < 2; nb++) {
            uint32_t b0 = Bp[nb * 8 * STRIDE + ko];
            uint32_t b1 = Bp[nb * 8 * STRIDE + ko + 4];
            mma_tf32(acc[nb][0], acc[nb][1], acc[nb][2], acc[nb][3],
                     a0, a1, a2, a3, b0, b1);
        }
    }

    // ---- epilogue ----
    // Thread owns rows {rw*16+g, +8}, cols cw*16 + nb*8 + 2*tig + {0,1}.
    {
        const float Cc = 0.05f;
        const float SQC = 0.22360679775f;     // sqrt(c)
        float y2v[4], yiv[4];
        #pragma unroll
        for (int nb = 0; nb < 2; nb++)
            #pragma unroll
            for (int c = 0; c < 2; c++) {
                int col = cw * 16 + nb * 8 + 2 * tig + c;
                y2v[nb * 2 + c] = sy2[col];
                yiv[nb * 2 + c] = syi[col];
            }
        #pragma unroll
        for (int half = 0; half < 2; half++) {
            int li = rw * 16 + g + half * 8;
            int gi = row0 + li;
            float x2  = sx2[li];
            float xin = rsqrtf(fmaxf(x2, 1e-24f));
            float B1  = 1.0f - Cc * x2;
            float s = 0.0f;
            #pragma unroll
            for (int nb = 0; nb < 2; nb++) {
                #pragma unroll
                for (int c = 0; c < 2; c++) {
                    int col = cw * 16 + nb * 8 + 2 * tig + c;
                    int gj  = col0 + col;
                    float d  = acc[nb][half * 2 + c];       // <z_i, z'_j>
                    float y2 = y2v[nb * 2 + c];
                    float A1  = 1.0f + Cc * (y2 - 2.0f * d);
                    float den = fmaxf(1.0f - 2.0f * Cc * d + Cc * Cc * x2 * y2, 1e-6f);
                    float num = fmaxf(A1 * A1 * x2 - 2.0f * A1 * B1 * d + B1 * B1 * y2, 0.0f);
                    float mn  = num * rsqrtf(fmaxf(num, 1e-37f));   // sqrt(num)
                    float t   = SQC * mn;
                    float pn  = den + t;
                    float qn  = fmaxf(den - t, 1e-6f * den);        // u <= 1-1e-6 guard
                    float l2  = lg2f(pn) - lg2f(qn);                // log2((1+u)/(1-u))
                    float cosv = d * xin * yiv[nb * 2 + c];
                    if (gi == gj) {
                        g_pos[gi] = 5.0f * cosv - 15.4993876f * l2; // 22.3607*ln2
                    } else {
                        s += ex2f(7.21347520f * cosv - 22.3606798f * l2);
                    }
                }
            }
            // reduce over tig group (lanes g*4 + {0..3} share the row)
            s += __shfl_xor_sync(0xffffffffu, s, 1);
            s += __shfl_xor_sync(0xffffffffu, s, 2);
            if (tig == 0) g_part[(blockIdx.x * 8 + cw) * MAXB + gi] = s;
        }
    }

    // ---- last CTA performs the final reduction (deterministic) ----
    __syncthreads();
    __threadfence();
    if (tid == 0) *s_rank = atomicAdd(&g_done, 1u);
    __syncthreads();
    unsigned nblk = gridDim.x * gridDim.y;
    if (*s_rank == nblk - 1) {
        int nparts = gridDim.x * 8;           // 64
        float s = 0.0f;
        for (int i = tid; i < B; i += 1024) {
            float dsum = 0.0f;
            #pragma unroll 8
            for (int p = 0; p < nparts; p++) dsum += g_part[p * MAXB + i];
            s += __logf(dsum) - g_pos[i];
        }
        #pragma unroll
        for (int o = 16; o; o >>= 1) s += __shfl_xor_sync(0xffffffffu, s, o);
        if (lane == 0) red[warp] = s;
        __syncthreads();
        if (tid == 0) {
            float tot = 0.0f;
            #pragma unroll
            for (int w = 0; w < 32; w++) tot += red[w];
            out[0] = tot / (float)B;
            g_done = 0;                         // reset for next graph replay
        }
    }
}

extern "C" void kernel_launch(void* const* d_in, const int* in_sizes, int n_in,
                              void* d_out, int out_size) {
    (void)n_in; (void)out_size;
    const float* z  = (const float*)d_in[0];
    const float* zp = (const float*)d_in[1];
    int B = in_sizes[0] / 128;

    int smem = (N_AS + N_BS + 384) * (int)sizeof(float);   // ~101 KB
    cudaFuncSetAttribute(hyp_pair, cudaFuncAttributeMaxDynamicSharedMemorySize, smem);
    dim3 grid(B / 128, B / 64);
    hyp_pair<<<grid, 1024, smem>>>(z, zp, (float*)d_out, B);
}

// round 16
// speedup vs baseline: 1.3170x; 1.3170x over previous
#include <cuda_runtime.h>
#include <cstdint>

#define MAXB 4096

static __device__ float g_pos[MAXB];
static __device__ float g_part[8 * MAXB];    // [colTile][row] partial row sums
static __device__ unsigned g_done = 0;

__device__ __forceinline__ float ex2f(float x) {
    float r; asm("ex2.approx.f32 %0, %1;" : "=f"(r) : "f"(x)); return r;
}
__device__ __forceinline__ float lg2f(float x) {
    float r; asm("lg2.approx.f32 %0, %1;" : "=f"(r) : "f"(x)); return r;
}

// m16n8k8 TF32 MMA: D = A(16x8,row) * B(8x8,col) + D, fp32 accum.
__device__ __forceinline__ void mma_tf32(float& c0, float& c1, float& c2, float& c3,
                                         uint32_t a0, uint32_t a1, uint32_t a2, uint32_t a3,
                                         uint32_t b0, uint32_t b1) {
    asm volatile(
        "mma.sync.aligned.m16n8k8.row.col.f32.tf32.tf32.f32 "
        "{%0,%1,%2,%3}, {%4,%5,%6,%7}, {%8,%9}, {%0,%1,%2,%3};"
        : "+f"(c0), "+f"(c1), "+f"(c2), "+f"(c3)
        : "r"(a0), "r"(a1), "r"(a2), "r"(a3), "r"(b0), "r"(b1));
}

#define STRIDE 132                 // 128 + 4 pad floats -> conflict-free fragment LDS
#define N_AS (64 * STRIDE)         // A: [row][k] natural, padded (33 KB)
#define N_BS (128 * STRIDE)        // B: [col][k] natural, padded (66 KB)

// ---------------- Fused kernel ----------------
// Tile 64 rows x 128 cols, 512 threads = 16 warps, grid (B/128, B/64) = 128 CTAs.
// Warp w: row-block rw = w&3 (16 rows), col-group cw = w>>2 (32 cols = 4 n-blocks).
// K loop: 16 steps of k=8 via mma.sync m16n8k8 tf32 (fallback HMMA on sm_103).
// Fills batch ALL 12 LDGs up front (MLP=12) before stores/norm reductions.
// cw partials are folded in-CTA via smem so the final tail reads 8 parts/row.
__global__ void __launch_bounds__(512, 1)
hyp_pair(const float* __restrict__ z, const float* __restrict__ zp,
         float* __restrict__ out, int B) {
    extern __shared__ float smem_f[];
    float* As  = smem_f;                      // 33 KB
    float* Bs  = smem_f + N_AS;               // 66 KB
    float* sx2 = Bs + N_BS;                   // 64
    float* sy2 = sx2 + 64;                    // 128
    float* syi = sy2 + 128;                   // 128
    unsigned* s_rank = (unsigned*)(syi + 128);
    float*    red    = (float*)(s_rank + 8);  // 16 floats
    float*    sred   = red + 16;              // 64 rows x 4 cw = 256 floats

    const int tid  = threadIdx.x;
    const int lane = tid & 31;
    const int warp = tid >> 5;                // 0..15
    const int row0 = blockIdx.y * 64;
    const int col0 = blockIdx.x * 128;

    // ---- fills: batch all LDGs first (independent, MLP=12), then process ----
    {
        const float4* zA = (const float4*)z + row0 * 32;
        const float4* zB = (const float4*)zp + col0 * 32;
        float4 va[4], vb[8];
        #pragma unroll
        for (int p = 0; p < 4; p++) va[p] = zA[(p * 16 + warp) * 32 + lane];
        #pragma unroll
        for (int p = 0; p < 8; p++) vb[p] = zB[(p * 16 + warp) * 32 + lane];

        #pragma unroll
        for (int p = 0; p < 4; p++) {
            int r = p * 16 + warp;
            float4 v = va[p];
            *(float4*)(As + r * STRIDE + 4 * lane) = v;
            float s = v.x * v.x + v.y * v.y + v.z * v.z + v.w * v.w;
            #pragma unroll
            for (int o = 16; o; o >>= 1) s += __shfl_xor_sync(0xffffffffu, s, o);
            if (lane == 0) sx2[r] = s;
        }
        #pragma unroll
        for (int p = 0; p < 8; p++) {
            int cj = p * 16 + warp;
            float4 v = vb[p];
            *(float4*)(Bs + cj * STRIDE + 4 * lane) = v;
            float s = v.x * v.x + v.y * v.y + v.z * v.z + v.w * v.w;
            #pragma unroll
            for (int o = 16; o; o >>= 1) s += __shfl_xor_sync(0xffffffffu, s, o);
            if (lane == 0) {
                sy2[cj] = s;
                syi[cj] = rsqrtf(fmaxf(s, 1e-24f));   // == 1/max(norm,1e-12)
            }
        }
    }
    __syncthreads();

    const int rw  = warp & 3;                 // row-block (16 rows)
    const int cw  = warp >> 2;                // col-group (32 cols)
    const int g   = lane >> 2;                // groupID
    const int tig = lane & 3;                 // threadID-in-group

    float acc[4][4];                          // [n-block][c-frag]
    #pragma unroll
    for (int nb = 0; nb < 4; nb++)
        #pragma unroll
        for (int c = 0; c < 4; c++) acc[nb][c] = 0.0f;

    const uint32_t* A0 = (const uint32_t*)(As + (rw * 16 + g) * STRIDE + tig);
    const uint32_t* A1 = A0 + 8 * STRIDE;
    const uint32_t* Bp = (const uint32_t*)(Bs + (cw * 32 + g) * STRIDE + tig);

    #pragma unroll
    for (int ks = 0; ks < 16; ks++) {
        const int ko = ks * 8;
        uint32_t a0 = A0[ko];
        uint32_t a1 = A1[ko];
        uint32_t a2 = A0[ko + 4];
        uint32_t a3 = A1[ko + 4];
        #pragma unroll
        for (int nb = 0; nb < 4; nb++) {
            uint32_t b0 = Bp[nb * 8 * STRIDE + ko];
            uint32_t b1 = Bp[nb * 8 * STRIDE + ko + 4];
            mma_tf32(acc[nb][0], acc[nb][1], acc[nb][2], acc[nb][3],
                     a0, a1, a2, a3, b0, b1);
        }
    }

    // ---- epilogue ----
    // Thread owns rows {rw*16+g, +8}, cols cw*32 + nb*8 + 2*tig + {0,1}.
    {
        const float Cc = 0.05f;
        const float SQC = 0.22360679775f;     // sqrt(c)
        float y2v[8], yiv[8];
        #pragma unroll
        for (int nb = 0; nb < 4; nb++)
            #pragma unroll
            for (int c = 0; c < 2; c++) {
                int col = cw * 32 + nb * 8 + 2 * tig + c;
                y2v[nb * 2 + c] = sy2[col];
                yiv[nb * 2 + c] = syi[col];
            }
        #pragma unroll
        for (int half = 0; half < 2; half++) {
            int li = rw * 16 + g + half * 8;
            int gi = row0 + li;
            float x2  = sx2[li];
            float xin = rsqrtf(fmaxf(x2, 1e-24f));
            float B1  = 1.0f - Cc * x2;
            float s = 0.0f;
            #pragma unroll
            for (int nb = 0; nb < 4; nb++) {
                #pragma unroll
                for (int c = 0; c < 2; c++) {
                    int col = cw * 32 + nb * 8 + 2 * tig + c;
                    int gj  = col0 + col;
                    float d  = acc[nb][half * 2 + c];       // <z_i, z'_j>
                    float y2 = y2v[nb * 2 + c];
                    float A1  = 1.0f + Cc * (y2 - 2.0f * d);
                    float den = fmaxf(1.0f - 2.0f * Cc * d + Cc * Cc * x2 * y2, 1e-6f);
                    float num = fmaxf(A1 * A1 * x2 - 2.0f * A1 * B1 * d + B1 * B1 * y2, 0.0f);
                    float mn  = num * rsqrtf(fmaxf(num, 1e-37f));   // sqrt(num)
                    float t   = SQC * mn;
                    float pn  = den + t;
                    float qn  = fmaxf(den - t, 1e-6f * den);        // u <= 1-1e-6 guard
                    float l2  = lg2f(pn) - lg2f(qn);                // log2((1+u)/(1-u))
                    float cosv = d * xin * yiv[nb * 2 + c];
                    if (gi == gj) {
                        g_pos[gi] = 5.0f * cosv - 15.4993876f * l2; // 22.3607*ln2
                    } else {
                        s += ex2f(7.21347520f * cosv - 22.3606798f * l2);
                    }
                }
            }
            // reduce over tig group (lanes g*4 + {0..3} share the row)
            s += __shfl_xor_sync(0xffffffffu, s, 1);
            s += __shfl_xor_sync(0xffffffffu, s, 2);
            if (tig == 0) sred[li * 4 + cw] = s;     // per-CTA cw partial
        }
    }

    // ---- fold the 4 cw partials per row, one g_part write per row ----
    __syncthreads();
    if (tid < 64) {
        float s = sred[tid * 4 + 0] + sred[tid * 4 + 1]
                + sred[tid * 4 + 2] + sred[tid * 4 + 3];
        g_part[blockIdx.x * MAXB + row0 + tid] = s;
    }

    // ---- last CTA performs the final reduction (deterministic) ----
    __syncthreads();
    __threadfence();
    if (tid == 0) *s_rank = atomicAdd(&g_done, 1u);
    __syncthreads();
    unsigned nblk = gridDim.x * gridDim.y;
    if (*s_rank == nblk - 1) {
        int nparts = gridDim.x;               // 8
        float s = 0.0f;
        for (int i = tid; i < B; i += 512) {
            float dsum = 0.0f;
            #pragma unroll 8
            for (int p = 0; p < nparts; p++) dsum += g_part[p * MAXB + i];
            s += __logf(dsum) - g_pos[i];
        }
        #pragma unroll
        for (int o = 16; o; o >>= 1) s += __shfl_xor_sync(0xffffffffu, s, o);
        if (lane == 0) red[warp] = s;
        __syncthreads();
        if (tid == 0) {
            float tot = 0.0f;
            #pragma unroll
            for (int w = 0; w < 16; w++) tot += red[w];
            out[0] = tot / (float)B;
            g_done = 0;                         // reset for next graph replay
        }
    }
}

extern "C" void kernel_launch(void* const* d_in, const int* in_sizes, int n_in,
                              void* d_out, int out_size) {
    (void)n_in; (void)out_size;
    const float* z  = (const float*)d_in[0];
    const float* zp = (const float*)d_in[1];
    int B = in_sizes[0] / 128;

    int smem = (N_AS + N_BS + 704) * (int)sizeof(float);   // ~102 KB
    cudaFuncSetAttribute(hyp_pair, cudaFuncAttributeMaxDynamicSharedMemorySize, smem);
    dim3 grid(B / 128, B / 64);
    hyp_pair<<<grid, 512, smem>>>(z, zp, (float*)d_out, B);
}